// round 16
// baseline (speedup 1.0000x reference)
#include <cuda_runtime.h>
#include <cstdint>

// ============================================================================
// EdgeClassifier: out = relu([emb[h], emb[t]] @ W1^T + b1) @ W2^T + b2
// E=500000, D=128, HIDDEN=256, NUM_CLASSES=32, fp32 in/out.
// R11 = R10 + group-decoupled GEMM1: warps 0-3 (N 0-127) and warps 4-7
// (N 128-255) each stage their own W1 chunk-half and sync on their own
// named barrier, so one group's MMAs cover the other's staging/barrier
// stalls (tensor pipe never fully drains). W2 read directly from L2 via
// LDG in GEMM2 (pre-converted tf32), removing its staging + a full sync.
// ============================================================================

#define TILE_M 128
#define DIMD   128
#define HID    256
#define NCLS   32
#define KC     32
#define NCHUNK (HID / KC)              // 8

#define SAW 260                        // A row stride (words), %32==4 conflict-free
#define SBW 36                         // W1 chunk row stride,  %32==4 conflict-free
#define SW2 264                        // W2 row stride (global, uint2 loads)

#define W1CH_WORDS (256 * SBW)         // 9216 words / chunk
#define W1CH_HALF  (W1CH_WORDS / 2)    // 4608 words / group half
#define W2_WORDS   (NCLS * SW2)        // 8448 words

// SMEM byte offsets
#define SM_B1    0
#define SM_B2    1024
#define SM_A     2048                              // 128 x 260 x 4 = 133120
#define SM_BUF0  (SM_A + TILE_M * SAW * 4)         // 135168
#define SM_BUF1  (SM_BUF0 + W1CH_WORDS * 4)        // 172032
#define SM_TOTAL (SM_BUF1 + W1CH_WORDS * 4)        // 208896

__device__ __align__(16) uint32_t g_w1t[NCHUNK * W1CH_WORDS];
__device__ __align__(16) uint32_t g_w2t[W2_WORDS];
__device__ int g_is64;

__device__ __forceinline__ uint32_t f2tf32(float f) {
    uint32_t r;
    asm("cvt.rna.tf32.f32 %0, %1;" : "=r"(r) : "f"(f));
    return r;
}
__device__ __forceinline__ uint32_t smem_u32(const void* p) {
    uint32_t a;
    asm("{ .reg .u64 t; cvta.to.shared.u64 t, %1; cvt.u32.u64 %0, t; }"
        : "=r"(a) : "l"(p));
    return a;
}
__device__ __forceinline__ void cp16(uint32_t dst, const void* src) {
    asm volatile("cp.async.cg.shared.global [%0], [%1], 16;"
                 :: "r"(dst), "l"(src) : "memory");
}
__device__ __forceinline__ void cp_commit() {
    asm volatile("cp.async.commit_group;" ::: "memory");
}
template <int N>
__device__ __forceinline__ void cp_wait() {
    asm volatile("cp.async.wait_group %0;" :: "n"(N) : "memory");
}
__device__ __forceinline__ void bar_grp(int id) {
    asm volatile("bar.sync %0, 128;" :: "r"(id) : "memory");
}
__device__ __forceinline__ void mma8(float* c, const uint32_t* a,
                                     uint32_t b0, uint32_t b1) {
    asm volatile(
        "mma.sync.aligned.m16n8k8.row.col.f32.tf32.tf32.f32 "
        "{%0,%1,%2,%3}, {%4,%5,%6,%7}, {%8,%9}, {%0,%1,%2,%3};"
        : "+f"(c[0]), "+f"(c[1]), "+f"(c[2]), "+f"(c[3])
        : "r"(a[0]), "r"(a[1]), "r"(a[2]), "r"(a[3]), "r"(b0), "r"(b1));
}
__device__ __forceinline__ void mma8s(float* c, uint32_t a0, uint32_t a1,
                                      uint32_t a2, uint32_t a3,
                                      uint32_t b0, uint32_t b1) {
    asm volatile(
        "mma.sync.aligned.m16n8k8.row.col.f32.tf32.tf32.f32 "
        "{%0,%1,%2,%3}, {%4,%5,%6,%7}, {%8,%9}, {%0,%1,%2,%3};"
        : "+f"(c[0]), "+f"(c[1]), "+f"(c[2]), "+f"(c[3])
        : "r"(a0), "r"(a1), "r"(a2), "r"(a3), "r"(b0), "r"(b1));
}

// ---- pre-kernel: idx-width detect + weight tf32 pre-convert ----------------
__global__ void prep_kernel(const float* __restrict__ W1,
                            const float* __restrict__ W2,
                            const unsigned int* __restrict__ p) {
    if (blockIdx.x == 0) {
        unsigned v = (threadIdx.x < 128) ? p[2 * threadIdx.x + 1] : 0u;
        int anynz = __syncthreads_or(v != 0u);
        if (threadIdx.x == 0) g_is64 = anynz ? 0 : 1;
    }
    const int i = blockIdx.x * 256 + threadIdx.x;
    if (i < NCHUNK * W1CH_WORDS) {
        const int kc = i / W1CH_WORDS, rem = i % W1CH_WORDS;
        const int row = rem / SBW, col = rem % SBW;
        g_w1t[i] = (col < KC) ? f2tf32(W1[row * HID + kc * KC + col]) : 0u;
    }
    if (i < W2_WORDS) {
        const int row = i / SW2, col = i % SW2;
        g_w2t[i] = (col < HID) ? f2tf32(W2[row * HID + col]) : 0u;
    }
}

// ============================================================================
__global__ __launch_bounds__(256, 1)
void edge_mlp_kernel(const float* __restrict__ emb,
                     const void*  __restrict__ eidx,
                     const float* __restrict__ b1,
                     const float* __restrict__ b2,
                     float* __restrict__ out,
                     int E) {
    extern __shared__ char smem[];
    float*    sb1 = (float*)(smem + SM_B1);
    float*    sb2 = (float*)(smem + SM_B2);
    uint32_t* Asm = (uint32_t*)(smem + SM_A);
    const uint32_t sb = smem_u32(smem);

    const int tid  = threadIdx.x;
    const int wid  = tid >> 5;
    const int lane = tid & 31;
    const int g    = lane >> 2;
    const int t    = lane & 3;
    const int tile = blockIdx.x;
    const int is64 = g_is64;

    const int grp   = wid >> 2;          // 0: N 0-127, 1: N 128-255
    const int gtid  = tid & 127;         // thread id within group
    const int barid = 1 + grp;           // named barrier per group

    sb1[tid] = b1[tid];
    if (tid < NCLS) sb2[tid] = b2[tid];

    // Stage this group's half of W1 chunk kc into buffer at dst.
    auto w1_issue_half = [&](int kc, uint32_t bufbase) {
        const uint32_t d = bufbase + (uint32_t)(grp * W1CH_HALF) * 4u;
        const uint32_t* src = g_w1t + kc * W1CH_WORDS + grp * W1CH_HALF;
        #pragma unroll
        for (int s = 0; s < W1CH_HALF / 4; s += 128)
            cp16(d + (s + gtid) * 16, src + (s + gtid) * 4);
        cp_commit();
    };

    // Prologue: each group stages its halves of chunks 0,1.
    w1_issue_half(0, sb + SM_BUF0);
    w1_issue_half(1, sb + SM_BUF1);

    // ---- Gather A[128][256]: warp handles one half (head/tail), rows
    //      r = (wid>>1) + 4j. Indices preloaded lane-parallel, shfl-broadcast.
    {
        const int half  = wid & 1;
        const int rbase = wid >> 1;
        long long node_l = -1;
        {
            const int r = rbase + 4 * lane;
            const int e = tile * TILE_M + r;
            if (e < E) {
                const long long ofs = half ? (long long)E + e : (long long)e;
                node_l = is64 ? ((const long long*)eidx)[ofs]
                              : (long long)((const int*)eidx)[ofs];
            }
        }
        #pragma unroll 4
        for (int j = 0; j < 32; j++) {
            const int r = rbase + 4 * j;
            const long long node = __shfl_sync(0xffffffffu, node_l, j);
            float4 v = make_float4(0.f, 0.f, 0.f, 0.f);
            if (node >= 0) v = ((const float4*)(emb + node * DIMD))[lane];
            *(uint4*)(Asm + r * SAW + half * 128 + lane * 4) =
                make_uint4(f2tf32(v.x), f2tf32(v.y), f2tf32(v.z), f2tf32(v.w));
        }
    }
    __syncthreads();                     // A tile visible to all warps

    // ---- GEMM1: D1[128,256] = A @ W1^T; warp tile 64x64 (2m x 4n warps) ----
    // Group-local pipeline: own buffer halves, own named barrier.
    const int mwb = (wid & 1) * 64;
    const int nwb = (wid >> 1) * 64;

    float acc[4][8][4];
    #pragma unroll
    for (int mt = 0; mt < 4; mt++)
        #pragma unroll
        for (int nt = 0; nt < 8; nt++)
            #pragma unroll
            for (int j = 0; j < 4; j++) acc[mt][nt][j] = 0.f;

    #pragma unroll 1
    for (int kc = 0; kc < NCHUNK; kc++) {
        if (kc == NCHUNK - 1) cp_wait<0>();
        else                  cp_wait<1>();
        bar_grp(barid);                  // group's chunk half visible

        const uint32_t* Bsm =
            (const uint32_t*)(smem + ((kc & 1) ? SM_BUF1 : SM_BUF0));

        #pragma unroll
        for (int s = 0; s < KC / 8; s++) {
            const int k0 = s * 8;
            const int ka = kc * KC + k0;
            uint32_t af[4][4];
            #pragma unroll
            for (int mt = 0; mt < 4; mt++) {
                const int r = mwb + mt * 16;
                af[mt][0] = Asm[(r + g)     * SAW + ka + t];
                af[mt][1] = Asm[(r + g + 8) * SAW + ka + t];
                af[mt][2] = Asm[(r + g)     * SAW + ka + t + 4];
                af[mt][3] = Asm[(r + g + 8) * SAW + ka + t + 4];
            }
            #pragma unroll
            for (int nt = 0; nt < 8; nt++) {
                const int n = nwb + nt * 8 + g;
                const uint32_t b0  = Bsm[n * SBW + k0 + t];
                const uint32_t b1r = Bsm[n * SBW + k0 + t + 4];
                #pragma unroll
                for (int mt = 0; mt < 4; mt++) mma8(acc[mt][nt], af[mt], b0, b1r);
            }
        }

        if (kc < NCHUNK - 2) {
            bar_grp(barid);              // group done reading buf[kc&1]
            w1_issue_half(kc + 2, sb + ((kc & 1) ? SM_BUF1 : SM_BUF0));
        }
    }

    // ---- GEMM2 from registers: per-warp K=64 partials, shuffle-free -------
    // k-relabel: thread t carries k=(2t,2t+1) in both operands. W2 fragments
    // loaded straight from pre-converted global (L2-hot), one nt ahead.
    float acc2p[4][4][4];
    #pragma unroll
    for (int mt = 0; mt < 4; mt++)
        #pragma unroll
        for (int n2b = 0; n2b < 4; n2b++)
            #pragma unroll
            for (int j = 0; j < 4; j++) acc2p[mt][n2b][j] = 0.f;

    uint2 bfc[4], bfn[4];
    #pragma unroll
    for (int n2b = 0; n2b < 4; n2b++)
        bfc[n2b] = *(const uint2*)(g_w2t + (n2b * 8 + g) * SW2 + nwb + 2 * t);

    #pragma unroll
    for (int nt = 0; nt < 8; nt++) {
        const int colb = nwb + nt * 8;
        if (nt < 7) {
            #pragma unroll
            for (int n2b = 0; n2b < 4; n2b++)
                bfn[n2b] = *(const uint2*)(g_w2t + (n2b * 8 + g) * SW2
                                           + colb + 8 + 2 * t);
        }
        const float bi0 = sb1[colb + 2 * t];
        const float bi1 = sb1[colb + 2 * t + 1];
        #pragma unroll
        for (int mt = 0; mt < 4; mt++) {
            const float* c = acc[mt][nt];
            const uint32_t h0 = f2tf32(fmaxf(c[0] + bi0, 0.f));
            const uint32_t h1 = f2tf32(fmaxf(c[1] + bi1, 0.f));
            const uint32_t h2 = f2tf32(fmaxf(c[2] + bi0, 0.f));
            const uint32_t h3 = f2tf32(fmaxf(c[3] + bi1, 0.f));
            #pragma unroll
            for (int n2b = 0; n2b < 4; n2b++)
                mma8s(acc2p[mt][n2b], h0, h2, h1, h3, bfc[n2b].x, bfc[n2b].y);
        }
        #pragma unroll
        for (int n2b = 0; n2b < 4; n2b++) bfc[n2b] = bfn[n2b];
    }

    // ---- Cross-warp K-reduce via scratch over dead A region ---------------
    __syncthreads();                     // all warps done reading A
    {
        float* scr = (float*)(smem + SM_A);
        #pragma unroll
        for (int mt = 0; mt < 4; mt++)
            #pragma unroll
            for (int n2b = 0; n2b < 4; n2b++)
                #pragma unroll
                for (int ci = 0; ci < 4; ci++)
                    scr[wid * 2048 + (mt * 16 + n2b * 4 + ci) * 32 + lane] =
                        acc2p[mt][n2b][ci];
        __syncthreads();

        const int mgrp = wid & 1;
        const int wq   = wid >> 1;
        #pragma unroll
        for (int n2b = 0; n2b < 4; n2b++) {
            float s[4];
            #pragma unroll
            for (int ci = 0; ci < 4; ci++) {
                const int reg = wq * 16 + n2b * 4 + ci;
                float v = scr[(0 * 2 + mgrp) * 2048 + reg * 32 + lane];
                v += scr[(1 * 2 + mgrp) * 2048 + reg * 32 + lane];
                v += scr[(2 * 2 + mgrp) * 2048 + reg * 32 + lane];
                v += scr[(3 * 2 + mgrp) * 2048 + reg * 32 + lane];
                s[ci] = v;
            }
            const int cc = n2b * 8 + 2 * t;
            const float bz0 = sb2[cc], bz1 = sb2[cc + 1];
            const int r0 = tile * TILE_M + mgrp * 64 + wq * 16 + g;
            if (r0 < E)
                *(float2*)(out + (size_t)r0 * NCLS + cc) =
                    make_float2(s[0] + bz0, s[1] + bz1);
            if (r0 + 8 < E)
                *(float2*)(out + (size_t)(r0 + 8) * NCLS + cc) =
                    make_float2(s[2] + bz0, s[3] + bz1);
        }
    }
}

// ============================================================================
extern "C" void kernel_launch(void* const* d_in, const int* in_sizes, int n_in,
                              void* d_out, int out_size) {
    const float* emb  = (const float*)d_in[0];
    const void*  eidx = d_in[1];
    const float* W1   = (const float*)d_in[2];
    const float* b1   = (const float*)d_in[3];
    const float* W2   = (const float*)d_in[4];
    const float* b2   = (const float*)d_in[5];
    float* out = (float*)d_out;

    const int E = in_sizes[1] / 2;
    const int tiles = (E + TILE_M - 1) / TILE_M;

    cudaFuncSetAttribute(edge_mlp_kernel,
                         cudaFuncAttributeMaxDynamicSharedMemorySize, SM_TOTAL);

    prep_kernel<<<(NCHUNK * W1CH_WORDS + 255) / 256, 256>>>(
        W1, W2, (const unsigned int*)eidx);
    edge_mlp_kernel<<<tiles, 256, SM_TOTAL>>>(emb, eidx, b1, b2, out, E);
}

// round 17
// speedup vs baseline: 1.5363x; 1.5363x over previous
#include <cuda_runtime.h>
#include <cstdint>

// ============================================================================
// EdgeClassifier: out = relu([emb[h], emb[t]] @ W1^T + b1) @ W2^T + b2
// E=500000, D=128, HIDDEN=256, NUM_CLASSES=32, fp32 in/out.
// R12 = R10 (best: 475.5us) + embedding table pre-converted to tf32 once per
// launch (g_embt) so the A gather becomes pure cp.async (16B/lane, no reg
// round-trip, no cvt) committed behind the W1 chunk-0/1 stages. GEMM1/GEMM2/
// reduce are byte-identical to R10.
// ============================================================================

#define TILE_M 128
#define DIMD   128
#define HID    256
#define NCLS   32
#define KC     32
#define NCHUNK (HID / KC)              // 8
#define MAX_EMB_WORDS 12800000         // 100000 nodes x 128 dims

#define SAW 260                        // A row stride (words), %32==4 conflict-free
#define SBW 36                         // W1 chunk row stride,  %32==4 conflict-free
#define SW2 264                        // W2 row stride (words)

#define W1CH_WORDS (256 * SBW)         // 9216 words / chunk
#define W2_WORDS   (NCLS * SW2)        // 8448 words

// SMEM byte offsets
#define SM_B1    0
#define SM_B2    1024
#define SM_A     2048                              // 128 x 260 x 4 = 133120
#define SM_BUF0  (SM_A + TILE_M * SAW * 4)         // 135168
#define SM_BUF1  (SM_BUF0 + W1CH_WORDS * 4)        // 172032
#define SM_TOTAL (SM_BUF1 + W1CH_WORDS * 4)        // 208896

__device__ __align__(16) uint32_t g_embt[MAX_EMB_WORDS];   // tf32 embeddings
__device__ __align__(16) uint32_t g_w1t[NCHUNK * W1CH_WORDS];
__device__ __align__(16) uint32_t g_w2t[W2_WORDS];
__device__ int g_is64;

__device__ __forceinline__ uint32_t f2tf32(float f) {
    uint32_t r;
    asm("cvt.rna.tf32.f32 %0, %1;" : "=r"(r) : "f"(f));
    return r;
}
__device__ __forceinline__ uint32_t smem_u32(const void* p) {
    uint32_t a;
    asm("{ .reg .u64 t; cvta.to.shared.u64 t, %1; cvt.u32.u64 %0, t; }"
        : "=r"(a) : "l"(p));
    return a;
}
__device__ __forceinline__ void cp16(uint32_t dst, const void* src) {
    asm volatile("cp.async.cg.shared.global [%0], [%1], 16;"
                 :: "r"(dst), "l"(src) : "memory");
}
__device__ __forceinline__ void cp_commit() {
    asm volatile("cp.async.commit_group;" ::: "memory");
}
template <int N>
__device__ __forceinline__ void cp_wait() {
    asm volatile("cp.async.wait_group %0;" :: "n"(N) : "memory");
}
__device__ __forceinline__ void mma8(float* c, const uint32_t* a,
                                     uint32_t b0, uint32_t b1) {
    asm volatile(
        "mma.sync.aligned.m16n8k8.row.col.f32.tf32.tf32.f32 "
        "{%0,%1,%2,%3}, {%4,%5,%6,%7}, {%8,%9}, {%0,%1,%2,%3};"
        : "+f"(c[0]), "+f"(c[1]), "+f"(c[2]), "+f"(c[3])
        : "r"(a[0]), "r"(a[1]), "r"(a[2]), "r"(a[3]), "r"(b0), "r"(b1));
}
__device__ __forceinline__ void mma8s(float* c, uint32_t a0, uint32_t a1,
                                      uint32_t a2, uint32_t a3,
                                      uint32_t b0, uint32_t b1) {
    asm volatile(
        "mma.sync.aligned.m16n8k8.row.col.f32.tf32.tf32.f32 "
        "{%0,%1,%2,%3}, {%4,%5,%6,%7}, {%8,%9}, {%0,%1,%2,%3};"
        : "+f"(c[0]), "+f"(c[1]), "+f"(c[2]), "+f"(c[3])
        : "r"(a0), "r"(a1), "r"(a2), "r"(a3), "r"(b0), "r"(b1));
}

// ---- pre-kernel: idx detect + weight & embedding tf32 pre-convert ----------
__global__ void prep_kernel(const float* __restrict__ W1,
                            const float* __restrict__ W2,
                            const float* __restrict__ emb,
                            const unsigned int* __restrict__ p,
                            int emb_words) {
    if (blockIdx.x == 0) {
        unsigned v = (threadIdx.x < 128) ? p[2 * threadIdx.x + 1] : 0u;
        int anynz = __syncthreads_or(v != 0u);
        if (threadIdx.x == 0) g_is64 = anynz ? 0 : 1;
    }
    const int i = blockIdx.x * 256 + threadIdx.x;
    // embeddings, float4-vectorized
    const int nv = emb_words >> 2;
    if (i < nv) {
        const float4 v = ((const float4*)emb)[i];
        ((uint4*)g_embt)[i] =
            make_uint4(f2tf32(v.x), f2tf32(v.y), f2tf32(v.z), f2tf32(v.w));
    }
    if (i < NCHUNK * W1CH_WORDS) {
        const int kc = i / W1CH_WORDS, rem = i % W1CH_WORDS;
        const int row = rem / SBW, col = rem % SBW;
        g_w1t[i] = (col < KC) ? f2tf32(W1[row * HID + kc * KC + col]) : 0u;
    }
    if (i < W2_WORDS) {
        const int row = i / SW2, col = i % SW2;
        g_w2t[i] = (col < HID) ? f2tf32(W2[row * HID + col]) : 0u;
    }
}

// ============================================================================
__global__ __launch_bounds__(256, 1)
void edge_mlp_kernel(const void*  __restrict__ eidx,
                     const float* __restrict__ b1,
                     const float* __restrict__ b2,
                     float* __restrict__ out,
                     int E) {
    extern __shared__ char smem[];
    float*    sb1 = (float*)(smem + SM_B1);
    float*    sb2 = (float*)(smem + SM_B2);
    uint32_t* Asm = (uint32_t*)(smem + SM_A);
    const uint32_t sb  = smem_u32(smem);
    const uint32_t sbA = sb + SM_A;

    const int tid  = threadIdx.x;
    const int wid  = tid >> 5;
    const int lane = tid & 31;
    const int g    = lane >> 2;
    const int t    = lane & 3;
    const int tile = blockIdx.x;
    const int is64 = g_is64;

    sb1[tid] = b1[tid];
    if (tid < NCLS) sb2[tid] = b2[tid];

    // ---- Load this warp's edge indices (latency overlapped with W1 issue) --
    const int half  = wid & 1;
    const int rbase = wid >> 1;
    long long node_l = -1;
    {
        const int r = rbase + 4 * lane;
        const int e = tile * TILE_M + r;
        if (e < E) {
            const long long ofs = half ? (long long)E + e : (long long)e;
            node_l = is64 ? ((const long long*)eidx)[ofs]
                          : (long long)((const int*)eidx)[ofs];
        }
    }

    // Prologue: async-stage W1 chunks 0,1.
    {
        const uint32_t d0 = sb + SM_BUF0, d1 = sb + SM_BUF1;
        #pragma unroll
        for (int s = 0; s < W1CH_WORDS / 4; s += 256)
            cp16(d0 + (s + tid) * 16, g_w1t + (s + tid) * 4);
        cp_commit();
        #pragma unroll
        for (int s = 0; s < W1CH_WORDS / 4; s += 256)
            cp16(d1 + (s + tid) * 16, g_w1t + W1CH_WORDS + (s + tid) * 4);
        cp_commit();
    }

    // ---- Gather A[128][256] via pure cp.async from tf32 table -------------
    // Warp covers one half (head/tail) of rows r = rbase + 4j; 16B per lane.
    #pragma unroll
    for (int j = 0; j < 32; j++) {
        const long long node = __shfl_sync(0xffffffffu, node_l, j);
        if (node >= 0) {
            const int r = rbase + 4 * j;
            cp16(sbA + (r * SAW + half * 128 + lane * 4) * 4,
                 g_embt + node * DIMD + lane * 4);
        }
    }
    cp_commit();

    // ---- GEMM1: D1[128,256] = A @ W1^T; warp tile 64x64 (2m x 4n warps) ----
    const int mwb = (wid & 1) * 64;
    const int nwb = (wid >> 1) * 64;

    float acc[4][8][4];
    #pragma unroll
    for (int mt = 0; mt < 4; mt++)
        #pragma unroll
        for (int nt = 0; nt < 8; nt++)
            #pragma unroll
            for (int j = 0; j < 4; j++) acc[mt][nt][j] = 0.f;

    #pragma unroll 1
    for (int kc = 0; kc < NCHUNK; kc++) {
        if (kc == 0) cp_wait<0>();       // W1 c0,c1 + gather all resident
        else         cp_wait<1>();
        __syncthreads();

        const uint32_t* Bsm =
            (const uint32_t*)(smem + ((kc & 1) ? SM_BUF1 : SM_BUF0));

        #pragma unroll
        for (int s = 0; s < KC / 8; s++) {
            const int k0 = s * 8;
            const int ka = kc * KC + k0;
            uint32_t af[4][4];
            #pragma unroll
            for (int mt = 0; mt < 4; mt++) {
                const int r = mwb + mt * 16;
                af[mt][0] = Asm[(r + g)     * SAW + ka + t];
                af[mt][1] = Asm[(r + g + 8) * SAW + ka + t];
                af[mt][2] = Asm[(r + g)     * SAW + ka + t + 4];
                af[mt][3] = Asm[(r + g + 8) * SAW + ka + t + 4];
            }
            #pragma unroll
            for (int nt = 0; nt < 8; nt++) {
                const int n = nwb + nt * 8 + g;
                const uint32_t b0  = Bsm[n * SBW + k0 + t];
                const uint32_t b1r = Bsm[n * SBW + k0 + t + 4];
                #pragma unroll
                for (int mt = 0; mt < 4; mt++) mma8(acc[mt][nt], af[mt], b0, b1r);
            }
        }
        __syncthreads();

        if (kc < NCHUNK - 2) {
            const uint32_t d = sb + ((kc & 1) ? SM_BUF1 : SM_BUF0);
            const uint32_t* src = g_w1t + (kc + 2) * W1CH_WORDS;
            #pragma unroll
            for (int s = 0; s < W1CH_WORDS / 4; s += 256)
                cp16(d + (s + tid) * 16, src + (s + tid) * 4);
            cp_commit();
        } else if (kc == NCHUNK - 2) {
            const uint32_t d = sb + SM_BUF0;     // buf0 free: prefetch W2
            for (int s = tid; s < W2_WORDS / 4; s += 256)
                cp16(d + s * 16, g_w2t + s * 4);
            cp_commit();
        }
    }

    // ---- GEMM2 from registers: per-warp K=64 partials, shuffle-free -------
    // k-relabel: thread t carries k=(2t,2t+1) in both operands.
    cp_wait<0>();                        // W2 resident in BUF0
    const uint32_t* Wsm = (const uint32_t*)(smem + SM_BUF0);

    float acc2p[4][4][4];
    #pragma unroll
    for (int mt = 0; mt < 4; mt++)
        #pragma unroll
        for (int n2b = 0; n2b < 4; n2b++)
            #pragma unroll
            for (int j = 0; j < 4; j++) acc2p[mt][n2b][j] = 0.f;

    #pragma unroll
    for (int nt = 0; nt < 8; nt++) {
        const int colb = nwb + nt * 8;
        const float bi0 = sb1[colb + 2 * t];
        const float bi1 = sb1[colb + 2 * t + 1];
        uint2 bf[4];
        #pragma unroll
        for (int n2b = 0; n2b < 4; n2b++)
            bf[n2b] = *(const uint2*)(Wsm + (n2b * 8 + g) * SW2 + colb + 2 * t);
        #pragma unroll
        for (int mt = 0; mt < 4; mt++) {
            const float* c = acc[mt][nt];
            const uint32_t h0 = f2tf32(fmaxf(c[0] + bi0, 0.f));
            const uint32_t h1 = f2tf32(fmaxf(c[1] + bi1, 0.f));
            const uint32_t h2 = f2tf32(fmaxf(c[2] + bi0, 0.f));
            const uint32_t h3 = f2tf32(fmaxf(c[3] + bi1, 0.f));
            #pragma unroll
            for (int n2b = 0; n2b < 4; n2b++)
                mma8s(acc2p[mt][n2b], h0, h2, h1, h3, bf[n2b].x, bf[n2b].y);
        }
    }

    // ---- Cross-warp K-reduce via scratch over dead A region ---------------
    {
        float* scr = (float*)(smem + SM_A);
        #pragma unroll
        for (int mt = 0; mt < 4; mt++)
            #pragma unroll
            for (int n2b = 0; n2b < 4; n2b++)
                #pragma unroll
                for (int ci = 0; ci < 4; ci++)
                    scr[wid * 2048 + (mt * 16 + n2b * 4 + ci) * 32 + lane] =
                        acc2p[mt][n2b][ci];
        __syncthreads();

        const int mgrp = wid & 1;
        const int wq   = wid >> 1;
        #pragma unroll
        for (int n2b = 0; n2b < 4; n2b++) {
            float s[4];
            #pragma unroll
            for (int ci = 0; ci < 4; ci++) {
                const int reg = wq * 16 + n2b * 4 + ci;
                float v = scr[(0 * 2 + mgrp) * 2048 + reg * 32 + lane];
                v += scr[(1 * 2 + mgrp) * 2048 + reg * 32 + lane];
                v += scr[(2 * 2 + mgrp) * 2048 + reg * 32 + lane];
                v += scr[(3 * 2 + mgrp) * 2048 + reg * 32 + lane];
                s[ci] = v;
            }
            const int cc = n2b * 8 + 2 * t;
            const float bz0 = sb2[cc], bz1 = sb2[cc + 1];
            const int r0 = tile * TILE_M + mgrp * 64 + wq * 16 + g;
            if (r0 < E)
                *(float2*)(out + (size_t)r0 * NCLS + cc) =
                    make_float2(s[0] + bz0, s[1] + bz1);
            if (r0 + 8 < E)
                *(float2*)(out + (size_t)(r0 + 8) * NCLS + cc) =
                    make_float2(s[2] + bz0, s[3] + bz1);
        }
    }
}

// ============================================================================
extern "C" void kernel_launch(void* const* d_in, const int* in_sizes, int n_in,
                              void* d_out, int out_size) {
    const float* emb  = (const float*)d_in[0];
    const void*  eidx = d_in[1];
    const float* W1   = (const float*)d_in[2];
    const float* b1   = (const float*)d_in[3];
    const float* W2   = (const float*)d_in[4];
    const float* b2   = (const float*)d_in[5];
    float* out = (float*)d_out;

    const int E = in_sizes[1] / 2;
    const int tiles = (E + TILE_M - 1) / TILE_M;
    int emb_words = in_sizes[0];
    if (emb_words > MAX_EMB_WORDS) emb_words = MAX_EMB_WORDS;

    const int prep_n = (emb_words >> 2) > NCHUNK * W1CH_WORDS
                     ? (emb_words >> 2) : NCHUNK * W1CH_WORDS;

    cudaFuncSetAttribute(edge_mlp_kernel,
                         cudaFuncAttributeMaxDynamicSharedMemorySize, SM_TOTAL);

    prep_kernel<<<(prep_n + 255) / 256, 256>>>(
        W1, W2, emb, (const unsigned int*)eidx, emb_words);
    edge_mlp_kernel<<<tiles, 256, SM_TOTAL>>>(eidx, b1, b2, out, E);
}